// round 2
// baseline (speedup 1.0000x reference)
#include <cuda_runtime.h>

// InvDiff: x[64, 4096, 256] fp32
//   d[b,l,f] = x[b,l+1,f] - x[b,l,f]                 (l in [0,4095))
//   y[b,l,f] = x[b,l+1,f] - x[b,0,f]  (l<4094), 0    (l==4094)
// Output = [d flattened | y flattened].
// Pure HBM-streaming kernel: 268MB read + 536MB write. Strategy: minimum
// traffic + streaming stores (__stcs) so L2 is reserved for the x-row
// reuse window, 2 l-rows per thread for fewer loads and front-batched MLP.

static constexpr int B  = 64;
static constexpr int L  = 4096;
static constexpr int F  = 256;
static constexpr int F4 = F / 4;          // 64 float4 per row
static constexpr int LD = L - 1;          // 4095 output rows

__device__ __forceinline__ float4 sub4(float4 a, float4 b) {
    float4 r; r.x = a.x - b.x; r.y = a.y - b.y; r.z = a.z - b.z; r.w = a.w - b.w;
    return r;
}

__global__ __launch_bounds__(256)
void invdiff_kernel(const float4* __restrict__ x, float4* __restrict__ out) {
    const int f  = threadIdx.x;                                    // 0..63
    const int l0 = (blockIdx.y * blockDim.y + threadIdx.y) * 2;    // even row
    const int b  = blockIdx.z;
    if (l0 >= LD) return;

    const int baseIn = b * (L * F4);
    const bool has2 = (l0 + 1) < LD;

    // Front-batch all loads (MLP). x0 stays L2/L1-hot (1KB per batch).
    const float4 x0 = x[baseIn + f];
    const float4 xa = x[baseIn +  l0      * F4 + f];
    const float4 xb = x[baseIn + (l0 + 1) * F4 + f];
    float4 xc;
    if (has2) xc = x[baseIn + (l0 + 2) * F4 + f];

    const int outIdx = b * (LD * F4) + l0 * F4 + f;
    const int D      = B * LD * F4;       // float4 count of d block

    // Row l0
    float4 d0 = sub4(xb, xa);
    float4 y0;
    if (l0 < LD - 1) y0 = sub4(xb, x0);
    else { y0.x = 0.f; y0.y = 0.f; y0.z = 0.f; y0.w = 0.f; }

    __stcs(&out[outIdx],     d0);
    __stcs(&out[D + outIdx], y0);

    // Row l0+1
    if (has2) {
        float4 d1 = sub4(xc, xb);
        float4 y1;
        if (l0 + 1 < LD - 1) y1 = sub4(xc, x0);
        else { y1.x = 0.f; y1.y = 0.f; y1.z = 0.f; y1.w = 0.f; }

        __stcs(&out[outIdx + F4],     d1);
        __stcs(&out[D + outIdx + F4], y1);
    }
}

extern "C" void kernel_launch(void* const* d_in, const int* in_sizes, int n_in,
                              void* d_out, int out_size) {
    const float4* x = (const float4*)d_in[0];
    float4* out = (float4*)d_out;

    // 2048 l-pairs, 4 pairs per block in y
    dim3 block(F4, 4, 1);                           // 256 threads
    dim3 grid(1, (LD / 2 + 1 + 3) / 4, B);          // 512 x 64 blocks
    invdiff_kernel<<<grid, block>>>(x, out);
}

// round 3
// speedup vs baseline: 1.0134x; 1.0134x over previous
#include <cuda_runtime.h>

// InvDiff: x[64, 4096, 256] fp32
//   d[b,l,f] = x[b,l+1,f] - x[b,l,f]                 (l in [0,4095))
//   y[b,l,f] = x[b,l+1,f] - x[b,0,f]  (l<4094), 0    (l==4094)
// Output = [d flattened | y flattened].
// HBM-bound at the traffic floor (268MB R + 536MB W). This version processes
// 4 l-rows per thread: 5 front-batched loads, then 4 consecutive d-stores
// followed by 4 consecutive y-stores (longer per-stream write bursts).

static constexpr int B    = 64;
static constexpr int L    = 4096;
static constexpr int F    = 256;
static constexpr int F4   = F / 4;        // 64 float4 per row
static constexpr int LD   = L - 1;        // 4095 output rows
static constexpr int RPT  = 4;            // rows per thread

__device__ __forceinline__ float4 sub4(float4 a, float4 b) {
    float4 r; r.x = a.x - b.x; r.y = a.y - b.y; r.z = a.z - b.z; r.w = a.w - b.w;
    return r;
}

__global__ __launch_bounds__(256)
void invdiff_kernel(const float4* __restrict__ x, float4* __restrict__ out) {
    const int f  = threadIdx.x;                                        // 0..63
    const int l0 = (blockIdx.y * blockDim.y + threadIdx.y) * RPT;      // base row
    const int b  = blockIdx.z;
    if (l0 >= LD) return;

    const int baseIn = b * (L * F4);

    // Front-batch loads: x rows l0 .. l0+RPT (RPT+1 rows), guarded at the tail.
    float4 xs[RPT + 1];
    xs[0] = x[baseIn + l0 * F4 + f];
#pragma unroll
    for (int r = 1; r <= RPT; r++) {
        if (l0 + r < L) xs[r] = x[baseIn + (l0 + r) * F4 + f];
    }
    const float4 x0 = x[baseIn + f];     // 1KB/batch, L1/L2-hot broadcast

    const int outIdx = b * (LD * F4) + l0 * F4 + f;
    const int D      = B * LD * F4;      // float4 count of d block

    // d-stores: consecutive addresses, one stream
#pragma unroll
    for (int r = 0; r < RPT; r++) {
        if (l0 + r < LD)
            out[outIdx + r * F4] = sub4(xs[r + 1], xs[r]);
    }

    // y-stores: consecutive addresses, other stream
#pragma unroll
    for (int r = 0; r < RPT; r++) {
        const int l = l0 + r;
        if (l < LD) {
            float4 yv;
            if (l < LD - 1) yv = sub4(xs[r + 1], x0);
            else { yv.x = 0.f; yv.y = 0.f; yv.z = 0.f; yv.w = 0.f; }
            out[D + outIdx + r * F4] = yv;
        }
    }
}

extern "C" void kernel_launch(void* const* d_in, const int* in_sizes, int n_in,
                              void* d_out, int out_size) {
    const float4* x = (const float4*)d_in[0];
    float4* out = (float4*)d_out;

    // ceil(4095 / 4) = 1024 thread-rows; 4 per block in y
    dim3 block(F4, 4, 1);                              // 256 threads
    dim3 grid(1, ( (LD + RPT - 1) / RPT + 3 ) / 4, B); // 256 x 64 blocks
    invdiff_kernel<<<grid, block>>>(x, out);
}

// round 5
// speedup vs baseline: 1.0137x; 1.0003x over previous
#include <cuda_runtime.h>

// InvDiff: x[64, 4096, 256] fp32
//   d[b,l,f] = x[b,l+1,f] - x[b,l,f]                 (l in [0,4095))
//   y[b,l,f] = x[b,l+1,f] - x[b,0,f]  (l<4094), 0    (l==4094)
// Output = [d flat | y flat]. HBM-bound at the traffic floor (268MB R +
// 536MB W, ~6.5 TB/s achieved). This round: L2::256B promotion hints on the
// sequential read stream + RPT=2 with high occupancy and no inner predication.

static constexpr int B   = 64;
static constexpr int L   = 4096;
static constexpr int F   = 256;
static constexpr int F4  = F / 4;         // 64 float4 per row
static constexpr int LD  = L - 1;         // 4095 output rows

__device__ __forceinline__ float4 ldg256(const float4* p) {
    float4 v;
    asm volatile("ld.global.nc.L2::256B.v4.f32 {%0,%1,%2,%3}, [%4];"
                 : "=f"(v.x), "=f"(v.y), "=f"(v.z), "=f"(v.w)
                 : "l"(p));
    return v;
}

__device__ __forceinline__ float4 sub4(float4 a, float4 b) {
    float4 r; r.x = a.x - b.x; r.y = a.y - b.y; r.z = a.z - b.z; r.w = a.w - b.w;
    return r;
}

__global__ __launch_bounds__(512)
void invdiff_kernel(const float4* __restrict__ x, float4* __restrict__ out) {
    const int f  = threadIdx.x;                                   // 0..63
    const int l0 = (blockIdx.y * blockDim.y + threadIdx.y) * 2;   // even row
    const int b  = blockIdx.z;
    if (l0 >= LD) return;

    const int baseIn = b * (L * F4);
    const int outIdx = b * (LD * F4) + l0 * F4 + f;
    const int D      = B * LD * F4;       // float4 count of d block

    const float4 x0 = __ldg(&x[baseIn + f]);   // 1KB/batch broadcast, cache-hot

    if (l0 + 2 < LD) {
        // Bulk path: no predication, 3 front-batched promoted loads.
        const float4 xa = ldg256(&x[baseIn +  l0      * F4 + f]);
        const float4 xb = ldg256(&x[baseIn + (l0 + 1) * F4 + f]);
        const float4 xc = ldg256(&x[baseIn + (l0 + 2) * F4 + f]);

        out[outIdx]          = sub4(xb, xa);
        out[outIdx + F4]     = sub4(xc, xb);
        out[D + outIdx]      = sub4(xb, x0);
        out[D + outIdx + F4] = sub4(xc, x0);
    } else {
        // Tail: rows near l = LD-1 (y's last row is zero; d may lack row 2).
        const float4 xa = __ldg(&x[baseIn + l0 * F4 + f]);
        const float4 xb = __ldg(&x[baseIn + (l0 + 1) * F4 + f]);

        out[outIdx] = sub4(xb, xa);
        float4 y0;
        if (l0 < LD - 1) y0 = sub4(xb, x0);
        else { y0.x = 0.f; y0.y = 0.f; y0.z = 0.f; y0.w = 0.f; }
        out[D + outIdx] = y0;

        if (l0 + 1 < LD) {
            const float4 xc = __ldg(&x[baseIn + (l0 + 2) * F4 + f]);
            out[outIdx + F4] = sub4(xc, xb);
            float4 y1;
            if (l0 + 1 < LD - 1) y1 = sub4(xc, x0);
            else { y1.x = 0.f; y1.y = 0.f; y1.z = 0.f; y1.w = 0.f; }
            out[D + outIdx + F4] = y1;
        }
    }
}

extern "C" void kernel_launch(void* const* d_in, const int* in_sizes, int n_in,
                              void* d_out, int out_size) {
    const float4* x = (const float4*)d_in[0];
    float4* out = (float4*)d_out;

    // 2048 l-pairs, 8 pairs per block in y -> 256 blocks in y
    dim3 block(F4, 8, 1);                            // 512 threads
    dim3 grid(1, (2048 + 7) / 8, B);                 // 256 x 64 blocks
    invdiff_kernel<<<grid, block>>>(x, out);
}